// round 2
// baseline (speedup 1.0000x reference)
#include <cuda_runtime.h>

#define N_NODESC 8192
#define N_EDGESC 262144
#define D_FEATC  512
#define NHIDC    32
#define LATENTC  16

// output layout (float elements)
#define ADJ_OFF  0ull
#define FEAT_OFF 67108864ull                 // 8192*8192
#define Z_OFF    71303168ull                 // + 8192*512

// ---------------- scratch (no allocations allowed) ----------------
__device__ alignas(16) float g_XW1 [N_NODESC * NHIDC];   // features @ Wg1 (pre-agg)
__device__ alignas(16) float g_HE  [N_NODESC * NHIDC];   // relu(features @ We1 + be1)
__device__ alignas(16) float g_AGG1[N_NODESC * NHIDC];
__device__ alignas(16) float g_XW2 [N_NODESC * LATENTC]; // h1 @ Wg2 (pre-agg)
__device__ alignas(16) float g_AGG2[N_NODESC * LATENTC];
__device__ alignas(16) float g_HD  [N_NODESC * NHIDC];   // relu(zx @ Wd1 + bd1)

// ---------------- helpers ----------------
__device__ __forceinline__ unsigned long long pack2(float lo, float hi) {
    unsigned long long r;
    asm("mov.b64 %0, {%1, %2};" : "=l"(r) : "f"(lo), "f"(hi));
    return r;
}
__device__ __forceinline__ void ffma2(unsigned long long& d, unsigned long long a, unsigned long long b) {
    asm("fma.rn.f32x2 %0, %1, %2, %0;" : "+l"(d) : "l"(a), "l"(b));
}
__device__ __forceinline__ float2 unpack2(unsigned long long v) {
    float2 r;
    asm("mov.b64 {%0, %1}, %2;" : "=f"(r.x), "=f"(r.y) : "l"(v));
    return r;
}
__device__ __forceinline__ void red_add_v4(float* p, float4 v) {
    asm volatile("red.global.add.v4.f32 [%0], {%1, %2, %3, %4};"
                 :: "l"(p), "f"(v.x), "f"(v.y), "f"(v.z), "f"(v.w) : "memory");
}
__device__ __forceinline__ float sigf(float x) {
    return __fdividef(1.0f, 1.0f + __expf(-x));
}

// ---------------- kernels ----------------

// zero the aggregation buffers
__global__ void k_zero() {
    int i = blockIdx.x * blockDim.x + threadIdx.x;   // 98304 float4 total
    float4 z = make_float4(0.f, 0.f, 0.f, 0.f);
    const int n1 = N_NODESC * NHIDC / 4;             // 65536
    const int n2 = n1 + N_NODESC * LATENTC / 4;      // 98304
    if (i < n1)      ((float4*)g_AGG1)[i] = z;
    else if (i < n2) ((float4*)g_AGG2)[i - n1] = z;
}

// fused:  g_XW1 = X @ Wg1   ;   g_HE = relu(X @ We1 + be1)
// GEMM [8192,512] x [512,64],  64x64 tile, 256 threads, thread tile 4x4, f32x2
__global__ void __launch_bounds__(256) k_transform1(
    const float* __restrict__ X, const float* __restrict__ Wg1,
    const float* __restrict__ We1, const float* __restrict__ be1)
{
    __shared__ float As[32][64];
    __shared__ float Bs[32][64];
    const int t = threadIdx.x;
    const int rowBase = blockIdx.x * 64;
    const int tx = t & 15, ty = t >> 4;

    unsigned long long acc[4][2];
#pragma unroll
    for (int i = 0; i < 4; i++) { acc[i][0] = 0ull; acc[i][1] = 0ull; }

    for (int k0 = 0; k0 < D_FEATC; k0 += 32) {
        // load A tile: 64 rows x 32 k  (transposed into As[k][row])
#pragma unroll
        for (int i = 0; i < 2; i++) {
            int idx = t + i * 256;          // 0..511
            int row = idx >> 3;
            int kk  = (idx & 7) * 4;
            float4 v = *(const float4*)(X + (size_t)(rowBase + row) * D_FEATC + k0 + kk);
            As[kk + 0][row] = v.x; As[kk + 1][row] = v.y;
            As[kk + 2][row] = v.z; As[kk + 3][row] = v.w;
        }
        // load B tile: 32 k x 64 cols (cols 0..31 = Wg1, 32..63 = We1)
#pragma unroll
        for (int i = 0; i < 8; i++) {
            int idx = t + i * 256;          // 0..2047
            int k = idx >> 6; int c = idx & 63;
            Bs[k][c] = (c < 32) ? Wg1[(k0 + k) * NHIDC + c]
                                : We1[(k0 + k) * NHIDC + (c - 32)];
        }
        __syncthreads();
#pragma unroll
        for (int k = 0; k < 32; k++) {
            unsigned long long a2[4];
#pragma unroll
            for (int i = 0; i < 4; i++) { float av = As[k][ty * 4 + i]; a2[i] = pack2(av, av); }
            unsigned long long b2a = *(const unsigned long long*)&Bs[k][tx * 4 + 0];
            unsigned long long b2b = *(const unsigned long long*)&Bs[k][tx * 4 + 2];
#pragma unroll
            for (int i = 0; i < 4; i++) { ffma2(acc[i][0], a2[i], b2a); ffma2(acc[i][1], a2[i], b2b); }
        }
        __syncthreads();
    }

    const int c0 = tx * 4;
#pragma unroll
    for (int i = 0; i < 4; i++) {
        int row = rowBase + ty * 4 + i;
        float2 v0 = unpack2(acc[i][0]);
        float2 v1 = unpack2(acc[i][1]);
        if (c0 < 32) {
            float4 o = make_float4(v0.x, v0.y, v1.x, v1.y);
            *(float4*)&g_XW1[row * NHIDC + c0] = o;
        } else {
            int cc = c0 - 32;
            float4 o;
            o.x = fmaxf(v0.x + be1[cc + 0], 0.f);
            o.y = fmaxf(v0.y + be1[cc + 1], 0.f);
            o.z = fmaxf(v1.x + be1[cc + 2], 0.f);
            o.w = fmaxf(v1.y + be1[cc + 3], 0.f);
            *(float4*)&g_HE[row * NHIDC + cc] = o;
        }
    }
}

// edge aggregation layer 1: g_AGG1[dst] += g_XW1[src] * w   (8 threads / edge)
__global__ void __launch_bounds__(256) k_agg1(
    const int* __restrict__ src, const int* __restrict__ dst, const float* __restrict__ w)
{
    int gid = blockIdx.x * 256 + threadIdx.x;
    int e = gid >> 3;
    if (e >= N_EDGESC) return;
    int c = (gid & 7) * 4;
    int s  = __ldg(&src[e]);
    int d  = __ldg(&dst[e]);
    float wt = __ldg(&w[e]);
    float4 v = *(const float4*)&g_XW1[s * NHIDC + c];
    v.x *= wt; v.y *= wt; v.z *= wt; v.w *= wt;
    red_add_v4(&g_AGG1[d * NHIDC + c], v);
}

// h1 = relu(agg1 + bg1) ; g_XW2 = h1 @ Wg2   (16 nodes / block)
__global__ void __launch_bounds__(256) k_layer2pre(
    const float* __restrict__ bg1, const float* __restrict__ Wg2)
{
    __shared__ float h1s[16][32];
    __shared__ float Wg2s[NHIDC * LATENTC];
    const int t = threadIdx.x;
    const int n0 = blockIdx.x * 16;
    for (int i = t; i < NHIDC * LATENTC; i += 256) Wg2s[i] = Wg2[i];
#pragma unroll
    for (int i = 0; i < 2; i++) {
        int idx = t + i * 256;               // 0..511
        int n = idx >> 5; int c = idx & 31;
        h1s[n][c] = fmaxf(g_AGG1[(n0 + n) * NHIDC + c] + bg1[c], 0.f);
    }
    __syncthreads();
    const int n = t >> 4, j = t & 15;
    float s = 0.f;
#pragma unroll
    for (int i = 0; i < NHIDC; i++) s += h1s[n][i] * Wg2s[i * LATENTC + j];
    g_XW2[(n0 + n) * LATENTC + j] = s;
}

// edge aggregation layer 2: g_AGG2[dst] += g_XW2[src] * w   (4 threads / edge)
__global__ void __launch_bounds__(256) k_agg2(
    const int* __restrict__ src, const int* __restrict__ dst, const float* __restrict__ w)
{
    int gid = blockIdx.x * 256 + threadIdx.x;
    int e = gid >> 2;
    if (e >= N_EDGESC) return;
    int c = (gid & 3) * 4;
    int s  = __ldg(&src[e]);
    int d  = __ldg(&dst[e]);
    float wt = __ldg(&w[e]);
    float4 v = *(const float4*)&g_XW2[s * LATENTC + c];
    v.x *= wt; v.y *= wt; v.z *= wt; v.w *= wt;
    red_add_v4(&g_AGG2[d * LATENTC + c], v);
}

// per node: za = relu(agg2+bg2); zx = relu(HE@We2+be2); z=[za|zx] -> out;
//           hd = relu(zx@Wd1+bd1) -> g_HD
__global__ void __launch_bounds__(128) k_node(
    const float* __restrict__ bg2, const float* __restrict__ We2,
    const float* __restrict__ be2, const float* __restrict__ Wd1,
    const float* __restrict__ bd1, float* __restrict__ out)
{
    __shared__ float We2s[512], Wd1s[512], be2s[16], bd1s[32], bg2s[16];
    const int t = threadIdx.x;
    for (int i = t; i < 512; i += 128) { We2s[i] = We2[i]; Wd1s[i] = Wd1[i]; }
    if (t < 16) { be2s[t] = be2[t]; bg2s[t] = bg2[t]; }
    if (t < 32) bd1s[t] = bd1[t];
    __syncthreads();

    const int n = blockIdx.x * 128 + t;
    float he[32];
#pragma unroll
    for (int i = 0; i < 8; i++) {
        float4 v = *(const float4*)&g_HE[n * NHIDC + i * 4];
        he[i * 4 + 0] = v.x; he[i * 4 + 1] = v.y; he[i * 4 + 2] = v.z; he[i * 4 + 3] = v.w;
    }
    float zx[16];
#pragma unroll
    for (int j = 0; j < 16; j++) {
        float s = be2s[j];
#pragma unroll
        for (int i = 0; i < 32; i++) s += he[i] * We2s[i * 16 + j];
        zx[j] = fmaxf(s, 0.f);
    }
    float* zo = out + Z_OFF + (size_t)n * 32;
#pragma unroll
    for (int j = 0; j < 16; j++) {
        float za = fmaxf(g_AGG2[n * LATENTC + j] + bg2s[j], 0.f);
        zo[j]      = za;
        zo[16 + j] = zx[j];
    }
#pragma unroll
    for (int i = 0; i < 32; i++) {
        float s = bd1s[i];
#pragma unroll
        for (int j = 0; j < 16; j++) s += zx[j] * Wd1s[j * 32 + i];
        g_HD[n * NHIDC + i] = fmaxf(s, 0.f);
    }
}

// feat_recon = relu(g_HD @ Wd2 + bd2)    (16 nodes / block, 256 threads)
__global__ void __launch_bounds__(256) k_feat(
    const float* __restrict__ Wd2, const float* __restrict__ bd2, float* __restrict__ out)
{
    __shared__ float hds[16][32];
    const int t = threadIdx.x;
    const int nb = blockIdx.x * 16;
#pragma unroll
    for (int i = 0; i < 2; i++) {
        int idx = t + i * 256;
        int n = idx >> 5; int c = idx & 31;
        hds[n][c] = g_HD[(nb + n) * NHIDC + c];
    }
    __syncthreads();

    const int c  = t & 127;            // col group: cols c*4 .. c*4+3
    const int ng = (t >> 7) * 8;       // node base within block: 0 or 8
    float4 acc[8];
#pragma unroll
    for (int nn = 0; nn < 8; nn++) acc[nn] = make_float4(0.f, 0.f, 0.f, 0.f);

#pragma unroll
    for (int k = 0; k < 32; k++) {
        float4 wv = __ldg((const float4*)&Wd2[k * D_FEATC + c * 4]);
#pragma unroll
        for (int nn = 0; nn < 8; nn++) {
            float h = hds[ng + nn][k];
            acc[nn].x += h * wv.x; acc[nn].y += h * wv.y;
            acc[nn].z += h * wv.z; acc[nn].w += h * wv.w;
        }
    }
    float4 b = __ldg((const float4*)&bd2[c * 4]);
#pragma unroll
    for (int nn = 0; nn < 8; nn++) {
        float4 o;
        o.x = fmaxf(acc[nn].x + b.x, 0.f);
        o.y = fmaxf(acc[nn].y + b.y, 0.f);
        o.z = fmaxf(acc[nn].z + b.z, 0.f);
        o.w = fmaxf(acc[nn].w + b.w, 0.f);
        *(float4*)&out[FEAT_OFF + (size_t)(nb + ng + nn) * D_FEATC + c * 4] = o;
    }
}

// adj = sigmoid(z z^T), symmetric: only upper-triangular 128x128 tiles, mirrored writes.
// 256 threads, thread tile 8x8, K=32, f32x2 packed FMA.
// Tile index decode (closed form): blocks enumerate pairs (it, jt), it <= jt, T=64 tiles.
__global__ void __launch_bounds__(256) k_adj(
    const float* __restrict__ zmat, float* __restrict__ out)
{
    __shared__ float Za[32][128];
    __shared__ float Zb[32][128];
    const int T = 64;
    // closed-form triangular decode: b = it*T - it*(it-1)/2 + (jt-it)
    const int b = blockIdx.x;
    // it = floor((2T+1 - sqrt((2T+1)^2 - 8b)) / 2)
    float disc = (2.0f * T + 1.0f) * (2.0f * T + 1.0f) - 8.0f * (float)b;
    int it = (int)((2.0f * T + 1.0f - sqrtf(disc)) * 0.5f);
    // correct any fp rounding
    while (it > 0 && b < it * T - (it * (it - 1)) / 2) it--;
    while (b >= (it + 1) * T - ((it + 1) * it) / 2) it++;
    const int jt = it + (b - (it * T - (it * (it - 1)) / 2));

    const int t = threadIdx.x;
    const int tx = t & 15, ty = t >> 4;

#pragma unroll
    for (int i = 0; i < 4; i++) {
        int idx = t + i * 256;              // 0..1023
        int row = idx >> 3;
        int kk  = (idx & 7) * 4;
        float4 va = *(const float4*)&zmat[(size_t)(it * 128 + row) * 32 + kk];
        Za[kk + 0][row] = va.x; Za[kk + 1][row] = va.y;
        Za[kk + 2][row] = va.z; Za[kk + 3][row] = va.w;
        float4 vb = *(const float4*)&zmat[(size_t)(jt * 128 + row) * 32 + kk];
        Zb[kk + 0][row] = vb.x; Zb[kk + 1][row] = vb.y;
        Zb[kk + 2][row] = vb.z; Zb[kk + 3][row] = vb.w;
    }
    __syncthreads();

    unsigned long long acc[8][4];
#pragma unroll
    for (int i = 0; i < 8; i++)
#pragma unroll
        for (int p = 0; p < 4; p++) acc[i][p] = 0ull;

#pragma unroll
    for (int k = 0; k < 32; k++) {
        unsigned long long a2[8], b2[4];
#pragma unroll
        for (int i = 0; i < 8; i++) { float av = Za[k][ty * 8 + i]; a2[i] = pack2(av, av); }
#pragma unroll
        for (int p = 0; p < 4; p++) b2[p] = *(const unsigned long long*)&Zb[k][tx * 8 + p * 2];
#pragma unroll
        for (int i = 0; i < 8; i++)
#pragma unroll
            for (int p = 0; p < 4; p++) ffma2(acc[i][p], a2[i], b2[p]);
    }

    float s[8][8];
#pragma unroll
    for (int i = 0; i < 8; i++)
#pragma unroll
        for (int p = 0; p < 4; p++) {
            float2 v = unpack2(acc[i][p]);
            s[i][p * 2 + 0] = sigf(v.x);
            s[i][p * 2 + 1] = sigf(v.y);
        }

    const size_t gi0 = (size_t)it * 128 + ty * 8;
    const size_t gj0 = (size_t)jt * 128 + tx * 8;
#pragma unroll
    for (int i = 0; i < 8; i++) {
        float* p = out + (gi0 + i) * (size_t)N_NODESC + gj0;
        *(float4*)(p + 0) = make_float4(s[i][0], s[i][1], s[i][2], s[i][3]);
        *(float4*)(p + 4) = make_float4(s[i][4], s[i][5], s[i][6], s[i][7]);
    }
    if (it != jt) {
#pragma unroll
        for (int j = 0; j < 8; j++) {
            float* p = out + (gj0 + j) * (size_t)N_NODESC + gi0;
            *(float4*)(p + 0) = make_float4(s[0][j], s[1][j], s[2][j], s[3][j]);
            *(float4*)(p + 4) = make_float4(s[4][j], s[5][j], s[6][j], s[7][j]);
        }
    }
}

// ---------------- launch ----------------
extern "C" void kernel_launch(void* const* d_in, const int* in_sizes, int n_in,
                              void* d_out, int out_size)
{
    const float* X   = (const float*)d_in[0];
    const int*   esrc= (const int*)  d_in[1];
    const int*   edst= (const int*)  d_in[2];
    const float* ew  = (const float*)d_in[3];
    const float* Wg1 = (const float*)d_in[4];
    const float* bg1 = (const float*)d_in[5];
    const float* Wg2 = (const float*)d_in[6];
    const float* bg2 = (const float*)d_in[7];
    const float* We1 = (const float*)d_in[8];
    const float* be1 = (const float*)d_in[9];
    const float* We2 = (const float*)d_in[10];
    const float* be2 = (const float*)d_in[11];
    const float* Wd1 = (const float*)d_in[12];
    const float* bd1 = (const float*)d_in[13];
    const float* Wd2 = (const float*)d_in[14];
    const float* bd2 = (const float*)d_in[15];
    float* out = (float*)d_out;

    k_zero      <<<384, 256>>>();
    k_transform1<<<128, 256>>>(X, Wg1, We1, be1);
    k_agg1      <<<8192, 256>>>(esrc, edst, ew);
    k_layer2pre <<<512, 256>>>(bg1, Wg2);
    k_agg2      <<<4096, 256>>>(esrc, edst, ew);
    k_node      <<<64, 128>>>(bg2, We2, be2, Wd1, bd1, out);
    k_feat      <<<512, 256>>>(Wd2, bd2, out);
    k_adj       <<<2080, 256>>>(out + Z_OFF, out);
}

// round 3
// speedup vs baseline: 1.0040x; 1.0040x over previous
#include <cuda_runtime.h>

#define N_NODESC 8192
#define N_EDGESC 262144
#define D_FEATC  512
#define NHIDC    32
#define LATENTC  16

// output layout (float elements)
#define ADJ_OFF  0ull
#define FEAT_OFF 67108864ull                 // 8192*8192
#define Z_OFF    71303168ull                 // + 8192*512

// ---------------- scratch (no allocations allowed) ----------------
__device__ alignas(16) float g_XW1 [N_NODESC * NHIDC];   // features @ Wg1 (pre-agg)
__device__ alignas(16) float g_HE  [N_NODESC * NHIDC];   // relu(features @ We1 + be1)
__device__ alignas(16) float g_AGG1[N_NODESC * NHIDC];
__device__ alignas(16) float g_XW2 [N_NODESC * LATENTC]; // h1 @ Wg2 (pre-agg)
__device__ alignas(16) float g_AGG2[N_NODESC * LATENTC];
__device__ alignas(16) float g_HD  [N_NODESC * NHIDC];   // relu(zx @ Wd1 + bd1)

// ---------------- helpers ----------------
__device__ __forceinline__ unsigned long long pack2(float lo, float hi) {
    unsigned long long r;
    asm("mov.b64 %0, {%1, %2};" : "=l"(r) : "f"(lo), "f"(hi));
    return r;
}
__device__ __forceinline__ void ffma2(unsigned long long& d, unsigned long long a, unsigned long long b) {
    asm("fma.rn.f32x2 %0, %1, %2, %0;" : "+l"(d) : "l"(a), "l"(b));
}
__device__ __forceinline__ float2 unpack2(unsigned long long v) {
    float2 r;
    asm("mov.b64 {%0, %1}, %2;" : "=f"(r.x), "=f"(r.y) : "l"(v));
    return r;
}
__device__ __forceinline__ void red_add_v4(float* p, float4 v) {
    asm volatile("red.global.add.v4.f32 [%0], {%1, %2, %3, %4};"
                 :: "l"(p), "f"(v.x), "f"(v.y), "f"(v.z), "f"(v.w) : "memory");
}
__device__ __forceinline__ float sigf(float x) {
    return __fdividef(1.0f, 1.0f + __expf(-x));
}

// ---------------- kernels ----------------

// fused:  zero agg buffers ; g_XW1 = X @ Wg1 ; g_HE = relu(X @ We1 + be1)
// GEMM [8192,512] x [512,64],  64x64 tile, 256 threads, thread tile 4x4, f32x2
__global__ void __launch_bounds__(256) k_transform1(
    const float* __restrict__ X, const float* __restrict__ Wg1,
    const float* __restrict__ We1, const float* __restrict__ be1)
{
    __shared__ float2 As2[32][64];     // duplicated (v,v)  16KB
    __shared__ float  Bs [32][64];     // 8KB
    const int t = threadIdx.x;

    // fused zeroing of aggregation buffers: 98304 float4 over 32768 threads
    {
        const float4 z4 = make_float4(0.f, 0.f, 0.f, 0.f);
        int gi = blockIdx.x * 256 + t;
#pragma unroll
        for (int q = 0; q < 3; q++) {
            int i = gi + q * 32768;                     // 0..98303
            if (i < 65536) ((float4*)g_AGG1)[i] = z4;
            else           ((float4*)g_AGG2)[i - 65536] = z4;
        }
    }

    const int rowBase = blockIdx.x * 64;
    const int tx = t & 15, ty = t >> 4;

    unsigned long long acc[4][2];
#pragma unroll
    for (int i = 0; i < 4; i++) { acc[i][0] = 0ull; acc[i][1] = 0ull; }

    for (int k0 = 0; k0 < D_FEATC; k0 += 32) {
        // load A tile: 64 rows x 32 k  (duplicated, transposed into As2[k][row])
#pragma unroll
        for (int i = 0; i < 2; i++) {
            int idx = t + i * 256;          // 0..511
            int row = idx >> 3;
            int kk  = (idx & 7) * 4;
            float4 v = *(const float4*)(X + (size_t)(rowBase + row) * D_FEATC + k0 + kk);
            As2[kk + 0][row] = make_float2(v.x, v.x);
            As2[kk + 1][row] = make_float2(v.y, v.y);
            As2[kk + 2][row] = make_float2(v.z, v.z);
            As2[kk + 3][row] = make_float2(v.w, v.w);
        }
        // load B tile: 32 k x 64 cols (cols 0..31 = Wg1, 32..63 = We1)
#pragma unroll
        for (int i = 0; i < 8; i++) {
            int idx = t + i * 256;          // 0..2047
            int k = idx >> 6; int c = idx & 63;
            Bs[k][c] = (c < 32) ? Wg1[(k0 + k) * NHIDC + c]
                                : We1[(k0 + k) * NHIDC + (c - 32)];
        }
        __syncthreads();
#pragma unroll
        for (int k = 0; k < 32; k++) {
            unsigned long long a2[4];
#pragma unroll
            for (int i = 0; i < 4; i++) a2[i] = *(const unsigned long long*)&As2[k][ty * 4 + i];
            unsigned long long b2a = *(const unsigned long long*)&Bs[k][tx * 4 + 0];
            unsigned long long b2b = *(const unsigned long long*)&Bs[k][tx * 4 + 2];
#pragma unroll
            for (int i = 0; i < 4; i++) { ffma2(acc[i][0], a2[i], b2a); ffma2(acc[i][1], a2[i], b2b); }
        }
        __syncthreads();
    }

    const int c0 = tx * 4;
#pragma unroll
    for (int i = 0; i < 4; i++) {
        int row = rowBase + ty * 4 + i;
        float2 v0 = unpack2(acc[i][0]);
        float2 v1 = unpack2(acc[i][1]);
        if (c0 < 32) {
            float4 o = make_float4(v0.x, v0.y, v1.x, v1.y);
            *(float4*)&g_XW1[row * NHIDC + c0] = o;
        } else {
            int cc = c0 - 32;
            float4 o;
            o.x = fmaxf(v0.x + be1[cc + 0], 0.f);
            o.y = fmaxf(v0.y + be1[cc + 1], 0.f);
            o.z = fmaxf(v1.x + be1[cc + 2], 0.f);
            o.w = fmaxf(v1.y + be1[cc + 3], 0.f);
            *(float4*)&g_HE[row * NHIDC + cc] = o;
        }
    }
}

// edge aggregation layer 1: g_AGG1[dst] += g_XW1[src] * w   (8 threads / edge)
__global__ void __launch_bounds__(256) k_agg1(
    const int* __restrict__ src, const int* __restrict__ dst, const float* __restrict__ w)
{
    int gid = blockIdx.x * 256 + threadIdx.x;
    int e = gid >> 3;
    if (e >= N_EDGESC) return;
    int c = (gid & 7) * 4;
    int s  = __ldg(&src[e]);
    int d  = __ldg(&dst[e]);
    float wt = __ldg(&w[e]);
    float4 v = *(const float4*)&g_XW1[s * NHIDC + c];
    v.x *= wt; v.y *= wt; v.z *= wt; v.w *= wt;
    red_add_v4(&g_AGG1[d * NHIDC + c], v);
}

// h1 = relu(agg1 + bg1) ; g_XW2 = h1 @ Wg2   (16 nodes / block)
__global__ void __launch_bounds__(256) k_layer2pre(
    const float* __restrict__ bg1, const float* __restrict__ Wg2)
{
    __shared__ float h1s[16][32];
    __shared__ float Wg2s[NHIDC * LATENTC];
    const int t = threadIdx.x;
    const int n0 = blockIdx.x * 16;
    for (int i = t; i < NHIDC * LATENTC; i += 256) Wg2s[i] = Wg2[i];
#pragma unroll
    for (int i = 0; i < 2; i++) {
        int idx = t + i * 256;               // 0..511
        int n = idx >> 5; int c = idx & 31;
        h1s[n][c] = fmaxf(g_AGG1[(n0 + n) * NHIDC + c] + bg1[c], 0.f);
    }
    __syncthreads();
    const int n = t >> 4, j = t & 15;
    float s = 0.f;
#pragma unroll
    for (int i = 0; i < NHIDC; i++) s += h1s[n][i] * Wg2s[i * LATENTC + j];
    g_XW2[(n0 + n) * LATENTC + j] = s;
}

// edge aggregation layer 2: g_AGG2[dst] += g_XW2[src] * w   (4 threads / edge)
__global__ void __launch_bounds__(256) k_agg2(
    const int* __restrict__ src, const int* __restrict__ dst, const float* __restrict__ w)
{
    int gid = blockIdx.x * 256 + threadIdx.x;
    int e = gid >> 2;
    if (e >= N_EDGESC) return;
    int c = (gid & 3) * 4;
    int s  = __ldg(&src[e]);
    int d  = __ldg(&dst[e]);
    float wt = __ldg(&w[e]);
    float4 v = *(const float4*)&g_XW2[s * LATENTC + c];
    v.x *= wt; v.y *= wt; v.z *= wt; v.w *= wt;
    red_add_v4(&g_AGG2[d * LATENTC + c], v);
}

// per node: za = relu(agg2+bg2); zx = relu(HE@We2+be2); z=[za|zx] -> out;
//           hd = relu(zx@Wd1+bd1) -> g_HD
__global__ void __launch_bounds__(128) k_node(
    const float* __restrict__ bg2, const float* __restrict__ We2,
    const float* __restrict__ be2, const float* __restrict__ Wd1,
    const float* __restrict__ bd1, float* __restrict__ out)
{
    __shared__ float We2s[512], Wd1s[512], be2s[16], bd1s[32], bg2s[16];
    const int t = threadIdx.x;
    for (int i = t; i < 512; i += 128) { We2s[i] = We2[i]; Wd1s[i] = Wd1[i]; }
    if (t < 16) { be2s[t] = be2[t]; bg2s[t] = bg2[t]; }
    if (t < 32) bd1s[t] = bd1[t];
    __syncthreads();

    const int n = blockIdx.x * 128 + t;
    float he[32];
#pragma unroll
    for (int i = 0; i < 8; i++) {
        float4 v = *(const float4*)&g_HE[n * NHIDC + i * 4];
        he[i * 4 + 0] = v.x; he[i * 4 + 1] = v.y; he[i * 4 + 2] = v.z; he[i * 4 + 3] = v.w;
    }
    float zx[16];
#pragma unroll
    for (int j = 0; j < 16; j++) {
        float s = be2s[j];
#pragma unroll
        for (int i = 0; i < 32; i++) s += he[i] * We2s[i * 16 + j];
        zx[j] = fmaxf(s, 0.f);
    }
    float* zo = out + Z_OFF + (size_t)n * 32;
#pragma unroll
    for (int j = 0; j < 16; j++) {
        float za = fmaxf(g_AGG2[n * LATENTC + j] + bg2s[j], 0.f);
        zo[j]      = za;
        zo[16 + j] = zx[j];
    }
#pragma unroll
    for (int i = 0; i < 32; i++) {
        float s = bd1s[i];
#pragma unroll
        for (int j = 0; j < 16; j++) s += zx[j] * Wd1s[j * 32 + i];
        g_HD[n * NHIDC + i] = fmaxf(s, 0.f);
    }
}

// feat_recon = relu(g_HD @ Wd2 + bd2)    (16 nodes / block, 256 threads, f32x2)
__global__ void __launch_bounds__(256) k_feat(
    const float* __restrict__ Wd2, const float* __restrict__ bd2, float* __restrict__ out)
{
    __shared__ float2 hds2[16][32];        // duplicated (v,v)
    const int t = threadIdx.x;
    const int nb = blockIdx.x * 16;
#pragma unroll
    for (int i = 0; i < 2; i++) {
        int idx = t + i * 256;
        int n = idx >> 5; int c = idx & 31;
        float v = g_HD[(nb + n) * NHIDC + c];
        hds2[n][c] = make_float2(v, v);
    }
    __syncthreads();

    const int c  = t & 127;            // col group: cols c*4 .. c*4+3
    const int ng = (t >> 7) * 8;       // node base within block: 0 or 8
    unsigned long long accA[8], accB[8];
#pragma unroll
    for (int nn = 0; nn < 8; nn++) { accA[nn] = 0ull; accB[nn] = 0ull; }

#pragma unroll
    for (int k = 0; k < 32; k++) {
        float4 wv = __ldg((const float4*)&Wd2[k * D_FEATC + c * 4]);
        unsigned long long w01 = pack2(wv.x, wv.y);
        unsigned long long w23 = pack2(wv.z, wv.w);
#pragma unroll
        for (int nn = 0; nn < 8; nn++) {
            unsigned long long h2 = *(const unsigned long long*)&hds2[ng + nn][k];
            ffma2(accA[nn], h2, w01);
            ffma2(accB[nn], h2, w23);
        }
    }
    float4 b = __ldg((const float4*)&bd2[c * 4]);
#pragma unroll
    for (int nn = 0; nn < 8; nn++) {
        float2 vA = unpack2(accA[nn]);
        float2 vB = unpack2(accB[nn]);
        float4 o;
        o.x = fmaxf(vA.x + b.x, 0.f);
        o.y = fmaxf(vA.y + b.y, 0.f);
        o.z = fmaxf(vB.x + b.z, 0.f);
        o.w = fmaxf(vB.y + b.w, 0.f);
        *(float4*)&out[FEAT_OFF + (size_t)(nb + ng + nn) * D_FEATC + c * 4] = o;
    }
}

// adj = sigmoid(z z^T), symmetric: only upper-triangular 128x128 tiles, mirrored writes.
// 256 threads, thread tile 8x8, K=32, f32x2 packed FMA.
// smem (dynamic, 52KB): Za2 = 32x128 float2 (A values duplicated) ;
//                       Zb  = 32x158 float  (B values, shear swizzle pc = c + 2*(c>>3))
// inner loop: 8 LDS.64 broadcast (a) + 4 conflict-free LDS.64 (b) + 32 FFMA2 -> FMA-bound.
#define ZB_W 158
__global__ void __launch_bounds__(256, 2) k_adj(
    const float* __restrict__ zmat, float* __restrict__ out)
{
    extern __shared__ char smraw[];
    float2* Za2 = (float2*)smraw;                       // [32][128] -> 32KB
    float*  Zb  = (float*)(smraw + 32 * 128 * 8);       // [32][158] -> 20224B

    const int T = 64;
    const int b = blockIdx.x;
    float disc = 129.0f * 129.0f - 8.0f * (float)b;
    int it = (int)((129.0f - sqrtf(disc)) * 0.5f);
    while (it > 0 && b < it * T - (it * (it - 1)) / 2) it--;
    while (b >= (it + 1) * T - ((it + 1) * it) / 2) it++;
    const int jt = it + (b - (it * T - (it * (it - 1)) / 2));

    const int t = threadIdx.x;
    const int tx = t & 15, ty = t >> 4;

#pragma unroll
    for (int i = 0; i < 4; i++) {
        int idx = t + i * 256;              // 0..1023
        int row = idx >> 3;                 // node within tile 0..127
        int kk  = (idx & 7) * 4;
        float4 va = *(const float4*)&zmat[(size_t)(it * 128 + row) * 32 + kk];
        Za2[(kk + 0) * 128 + row] = make_float2(va.x, va.x);
        Za2[(kk + 1) * 128 + row] = make_float2(va.y, va.y);
        Za2[(kk + 2) * 128 + row] = make_float2(va.z, va.z);
        Za2[(kk + 3) * 128 + row] = make_float2(va.w, va.w);
        float4 vb = *(const float4*)&zmat[(size_t)(jt * 128 + row) * 32 + kk];
        int pc = row + 2 * (row >> 3);
        Zb[(kk + 0) * ZB_W + pc] = vb.x;
        Zb[(kk + 1) * ZB_W + pc] = vb.y;
        Zb[(kk + 2) * ZB_W + pc] = vb.z;
        Zb[(kk + 3) * ZB_W + pc] = vb.w;
    }
    __syncthreads();

    unsigned long long acc[8][4];
#pragma unroll
    for (int i = 0; i < 8; i++)
#pragma unroll
        for (int p = 0; p < 4; p++) acc[i][p] = 0ull;

#pragma unroll
    for (int k = 0; k < 32; k++) {
        unsigned long long a2[8], b2[4];
#pragma unroll
        for (int i = 0; i < 8; i++)
            a2[i] = *(const unsigned long long*)&Za2[k * 128 + ty * 8 + i];
#pragma unroll
        for (int p = 0; p < 4; p++)
            b2[p] = *(const unsigned long long*)&Zb[k * ZB_W + tx * 10 + p * 2];
#pragma unroll
        for (int i = 0; i < 8; i++)
#pragma unroll
            for (int p = 0; p < 4; p++) ffma2(acc[i][p], a2[i], b2[p]);
    }

    float s[8][8];
#pragma unroll
    for (int i = 0; i < 8; i++)
#pragma unroll
        for (int p = 0; p < 4; p++) {
            float2 v = unpack2(acc[i][p]);
            s[i][p * 2 + 0] = sigf(v.x);
            s[i][p * 2 + 1] = sigf(v.y);
        }

    const size_t gi0 = (size_t)it * 128 + ty * 8;
    const size_t gj0 = (size_t)jt * 128 + tx * 8;
#pragma unroll
    for (int i = 0; i < 8; i++) {
        float* p = out + (gi0 + i) * (size_t)N_NODESC + gj0;
        *(float4*)(p + 0) = make_float4(s[i][0], s[i][1], s[i][2], s[i][3]);
        *(float4*)(p + 4) = make_float4(s[i][4], s[i][5], s[i][6], s[i][7]);
    }
    if (it != jt) {
#pragma unroll
        for (int j = 0; j < 8; j++) {
            float* p = out + (gj0 + j) * (size_t)N_NODESC + gi0;
            *(float4*)(p + 0) = make_float4(s[0][j], s[1][j], s[2][j], s[3][j]);
            *(float4*)(p + 4) = make_float4(s[4][j], s[5][j], s[6][j], s[7][j]);
        }
    }
}

// ---------------- launch ----------------
extern "C" void kernel_launch(void* const* d_in, const int* in_sizes, int n_in,
                              void* d_out, int out_size)
{
    const float* X   = (const float*)d_in[0];
    const int*   esrc= (const int*)  d_in[1];
    const int*   edst= (const int*)  d_in[2];
    const float* ew  = (const float*)d_in[3];
    const float* Wg1 = (const float*)d_in[4];
    const float* bg1 = (const float*)d_in[5];
    const float* Wg2 = (const float*)d_in[6];
    const float* bg2 = (const float*)d_in[7];
    const float* We1 = (const float*)d_in[8];
    const float* be1 = (const float*)d_in[9];
    const float* We2 = (const float*)d_in[10];
    const float* be2 = (const float*)d_in[11];
    const float* Wd1 = (const float*)d_in[12];
    const float* bd1 = (const float*)d_in[13];
    const float* Wd2 = (const float*)d_in[14];
    const float* bd2 = (const float*)d_in[15];
    float* out = (float*)d_out;

    const int adjSmem = 32 * 128 * 8 + 32 * ZB_W * 4;   // 52992 bytes
    cudaFuncSetAttribute(k_adj, cudaFuncAttributeMaxDynamicSharedMemorySize, adjSmem);

    k_transform1<<<128, 256>>>(X, Wg1, We1, be1);
    k_agg1      <<<8192, 256>>>(esrc, edst, ew);
    k_layer2pre <<<512, 256>>>(bg1, Wg2);
    k_agg2      <<<4096, 256>>>(esrc, edst, ew);
    k_node      <<<64, 128>>>(bg2, We2, be2, Wd1, bd1, out);
    k_feat      <<<512, 256>>>(Wd2, bd2, out);
    k_adj       <<<2080, 256, adjSmem>>>(out + Z_OFF, out);
}

// round 6
// speedup vs baseline: 1.2928x; 1.2876x over previous
#include <cuda_runtime.h>
#include <cuda_bf16.h>
#include <cstdint>

#define N_NODESC 8192
#define N_EDGESC 262144
#define D_FEATC  512
#define NHIDC    32
#define LATENTC  16

// output layout (float elements)
#define ADJ_OFF  0ull
#define FEAT_OFF 67108864ull                 // 8192*8192
#define Z_OFF    71303168ull                 // + 8192*512

// ---------------- scratch (no allocations allowed) ----------------
__device__ alignas(16) float g_XW1 [N_NODESC * NHIDC];
__device__ alignas(16) float g_HE  [N_NODESC * NHIDC];
__device__ alignas(16) float g_AGG1[N_NODESC * NHIDC];
__device__ alignas(16) float g_XW2 [N_NODESC * LATENTC];
__device__ alignas(16) float g_AGG2[N_NODESC * LATENTC];
__device__ alignas(16) float g_HD  [N_NODESC * NHIDC];

// ---------------- helpers ----------------
__device__ __forceinline__ unsigned long long pack2(float lo, float hi) {
    unsigned long long r;
    asm("mov.b64 %0, {%1, %2};" : "=l"(r) : "f"(lo), "f"(hi));
    return r;
}
__device__ __forceinline__ void ffma2(unsigned long long& d, unsigned long long a, unsigned long long b) {
    asm("fma.rn.f32x2 %0, %1, %2, %0;" : "+l"(d) : "l"(a), "l"(b));
}
__device__ __forceinline__ float2 unpack2(unsigned long long v) {
    float2 r;
    asm("mov.b64 {%0, %1}, %2;" : "=f"(r.x), "=f"(r.y) : "l"(v));
    return r;
}
__device__ __forceinline__ void red_add_v4(float* p, float4 v) {
    asm volatile("red.global.add.v4.f32 [%0], {%1, %2, %3, %4};"
                 :: "l"(p), "f"(v.x), "f"(v.y), "f"(v.z), "f"(v.w) : "memory");
}
__device__ __forceinline__ float sigf(float x) {
    return __fdividef(1.0f, 1.0f + __expf(-x));
}
__device__ __forceinline__ uint32_t smem_u32(const void* p) {
    uint32_t a;
    asm("{ .reg .u64 t; cvta.to.shared.u64 t, %1; cvt.u32.u64 %0, t; }" : "=r"(a) : "l"(p));
    return a;
}
__device__ __forceinline__ void ldsm_x4(uint32_t& r0, uint32_t& r1, uint32_t& r2, uint32_t& r3,
                                        uint32_t addr) {
    asm volatile("ldmatrix.sync.aligned.m8n8.x4.shared.b16 {%0,%1,%2,%3}, [%4];"
                 : "=r"(r0), "=r"(r1), "=r"(r2), "=r"(r3) : "r"(addr));
}
__device__ __forceinline__ void mma_16816(float* c, const uint32_t* a, const uint32_t* b) {
    asm volatile(
        "mma.sync.aligned.m16n8k16.row.col.f32.bf16.bf16.f32 "
        "{%0,%1,%2,%3}, {%4,%5,%6,%7}, {%8,%9}, {%0,%1,%2,%3};"
        : "+f"(c[0]), "+f"(c[1]), "+f"(c[2]), "+f"(c[3])
        : "r"(a[0]), "r"(a[1]), "r"(a[2]), "r"(a[3]), "r"(b[0]), "r"(b[1]));
}

// ---------------- kernels (non-adj: unchanged from R3, proven passing) ----------------

__global__ void __launch_bounds__(256) k_transform1(
    const float* __restrict__ X, const float* __restrict__ Wg1,
    const float* __restrict__ We1, const float* __restrict__ be1)
{
    __shared__ float2 As2[32][64];
    __shared__ float  Bs [32][64];
    const int t = threadIdx.x;

    {
        const float4 z4 = make_float4(0.f, 0.f, 0.f, 0.f);
        int gi = blockIdx.x * 256 + t;
#pragma unroll
        for (int q = 0; q < 3; q++) {
            int i = gi + q * 32768;
            if (i < 65536) ((float4*)g_AGG1)[i] = z4;
            else           ((float4*)g_AGG2)[i - 65536] = z4;
        }
    }

    const int rowBase = blockIdx.x * 64;
    const int tx = t & 15, ty = t >> 4;

    unsigned long long acc[4][2];
#pragma unroll
    for (int i = 0; i < 4; i++) { acc[i][0] = 0ull; acc[i][1] = 0ull; }

    for (int k0 = 0; k0 < D_FEATC; k0 += 32) {
#pragma unroll
        for (int i = 0; i < 2; i++) {
            int idx = t + i * 256;
            int row = idx >> 3;
            int kk  = (idx & 7) * 4;
            float4 v = *(const float4*)(X + (size_t)(rowBase + row) * D_FEATC + k0 + kk);
            As2[kk + 0][row] = make_float2(v.x, v.x);
            As2[kk + 1][row] = make_float2(v.y, v.y);
            As2[kk + 2][row] = make_float2(v.z, v.z);
            As2[kk + 3][row] = make_float2(v.w, v.w);
        }
#pragma unroll
        for (int i = 0; i < 8; i++) {
            int idx = t + i * 256;
            int k = idx >> 6; int c = idx & 63;
            Bs[k][c] = (c < 32) ? Wg1[(k0 + k) * NHIDC + c]
                                : We1[(k0 + k) * NHIDC + (c - 32)];
        }
        __syncthreads();
#pragma unroll
        for (int k = 0; k < 32; k++) {
            unsigned long long a2[4];
#pragma unroll
            for (int i = 0; i < 4; i++) a2[i] = *(const unsigned long long*)&As2[k][ty * 4 + i];
            unsigned long long b2a = *(const unsigned long long*)&Bs[k][tx * 4 + 0];
            unsigned long long b2b = *(const unsigned long long*)&Bs[k][tx * 4 + 2];
#pragma unroll
            for (int i = 0; i < 4; i++) { ffma2(acc[i][0], a2[i], b2a); ffma2(acc[i][1], a2[i], b2b); }
        }
        __syncthreads();
    }

    const int c0 = tx * 4;
#pragma unroll
    for (int i = 0; i < 4; i++) {
        int row = rowBase + ty * 4 + i;
        float2 v0 = unpack2(acc[i][0]);
        float2 v1 = unpack2(acc[i][1]);
        if (c0 < 32) {
            *(float4*)&g_XW1[row * NHIDC + c0] = make_float4(v0.x, v0.y, v1.x, v1.y);
        } else {
            int cc = c0 - 32;
            float4 o;
            o.x = fmaxf(v0.x + be1[cc + 0], 0.f);
            o.y = fmaxf(v0.y + be1[cc + 1], 0.f);
            o.z = fmaxf(v1.x + be1[cc + 2], 0.f);
            o.w = fmaxf(v1.y + be1[cc + 3], 0.f);
            *(float4*)&g_HE[row * NHIDC + cc] = o;
        }
    }
}

__global__ void __launch_bounds__(256) k_agg1(
    const int* __restrict__ src, const int* __restrict__ dst, const float* __restrict__ w)
{
    int gid = blockIdx.x * 256 + threadIdx.x;
    int e = gid >> 3;
    if (e >= N_EDGESC) return;
    int c = (gid & 7) * 4;
    int s  = __ldg(&src[e]);
    int d  = __ldg(&dst[e]);
    float wt = __ldg(&w[e]);
    float4 v = *(const float4*)&g_XW1[s * NHIDC + c];
    v.x *= wt; v.y *= wt; v.z *= wt; v.w *= wt;
    red_add_v4(&g_AGG1[d * NHIDC + c], v);
}

__global__ void __launch_bounds__(256) k_layer2pre(
    const float* __restrict__ bg1, const float* __restrict__ Wg2)
{
    __shared__ float h1s[16][32];
    __shared__ float Wg2s[NHIDC * LATENTC];
    const int t = threadIdx.x;
    const int n0 = blockIdx.x * 16;
    for (int i = t; i < NHIDC * LATENTC; i += 256) Wg2s[i] = Wg2[i];
#pragma unroll
    for (int i = 0; i < 2; i++) {
        int idx = t + i * 256;
        int n = idx >> 5; int c = idx & 31;
        h1s[n][c] = fmaxf(g_AGG1[(n0 + n) * NHIDC + c] + bg1[c], 0.f);
    }
    __syncthreads();
    const int n = t >> 4, j = t & 15;
    float s = 0.f;
#pragma unroll
    for (int i = 0; i < NHIDC; i++) s += h1s[n][i] * Wg2s[i * LATENTC + j];
    g_XW2[(n0 + n) * LATENTC + j] = s;
}

__global__ void __launch_bounds__(256) k_agg2(
    const int* __restrict__ src, const int* __restrict__ dst, const float* __restrict__ w)
{
    int gid = blockIdx.x * 256 + threadIdx.x;
    int e = gid >> 2;
    if (e >= N_EDGESC) return;
    int c = (gid & 3) * 4;
    int s  = __ldg(&src[e]);
    int d  = __ldg(&dst[e]);
    float wt = __ldg(&w[e]);
    float4 v = *(const float4*)&g_XW2[s * LATENTC + c];
    v.x *= wt; v.y *= wt; v.z *= wt; v.w *= wt;
    red_add_v4(&g_AGG2[d * LATENTC + c], v);
}

__global__ void __launch_bounds__(128) k_node(
    const float* __restrict__ bg2, const float* __restrict__ We2,
    const float* __restrict__ be2, const float* __restrict__ Wd1,
    const float* __restrict__ bd1, float* __restrict__ out)
{
    __shared__ float We2s[512], Wd1s[512], be2s[16], bd1s[32], bg2s[16];
    const int t = threadIdx.x;
    for (int i = t; i < 512; i += 128) { We2s[i] = We2[i]; Wd1s[i] = Wd1[i]; }
    if (t < 16) { be2s[t] = be2[t]; bg2s[t] = bg2[t]; }
    if (t < 32) bd1s[t] = bd1[t];
    __syncthreads();

    const int n = blockIdx.x * 128 + t;
    float he[32];
#pragma unroll
    for (int i = 0; i < 8; i++) {
        float4 v = *(const float4*)&g_HE[n * NHIDC + i * 4];
        he[i * 4 + 0] = v.x; he[i * 4 + 1] = v.y; he[i * 4 + 2] = v.z; he[i * 4 + 3] = v.w;
    }
    float zx[16];
#pragma unroll
    for (int j = 0; j < 16; j++) {
        float s = be2s[j];
#pragma unroll
        for (int i = 0; i < 32; i++) s += he[i] * We2s[i * 16 + j];
        zx[j] = fmaxf(s, 0.f);
    }
    float* zo = out + Z_OFF + (size_t)n * 32;
#pragma unroll
    for (int j = 0; j < 16; j++) {
        float za = fmaxf(g_AGG2[n * LATENTC + j] + bg2s[j], 0.f);
        zo[j]      = za;
        zo[16 + j] = zx[j];
    }
#pragma unroll
    for (int i = 0; i < 32; i++) {
        float s = bd1s[i];
#pragma unroll
        for (int j = 0; j < 16; j++) s += zx[j] * Wd1s[j * 32 + i];
        g_HD[n * NHIDC + i] = fmaxf(s, 0.f);
    }
}

__global__ void __launch_bounds__(256) k_feat(
    const float* __restrict__ Wd2, const float* __restrict__ bd2, float* __restrict__ out)
{
    __shared__ float2 hds2[16][32];
    const int t = threadIdx.x;
    const int nb = blockIdx.x * 16;
#pragma unroll
    for (int i = 0; i < 2; i++) {
        int idx = t + i * 256;
        int n = idx >> 5; int c = idx & 31;
        float v = g_HD[(nb + n) * NHIDC + c];
        hds2[n][c] = make_float2(v, v);
    }
    __syncthreads();

    const int c  = t & 127;
    const int ng = (t >> 7) * 8;
    unsigned long long accA[8], accB[8];
#pragma unroll
    for (int nn = 0; nn < 8; nn++) { accA[nn] = 0ull; accB[nn] = 0ull; }

#pragma unroll
    for (int k = 0; k < 32; k++) {
        float4 wv = __ldg((const float4*)&Wd2[k * D_FEATC + c * 4]);
        unsigned long long w01 = pack2(wv.x, wv.y);
        unsigned long long w23 = pack2(wv.z, wv.w);
#pragma unroll
        for (int nn = 0; nn < 8; nn++) {
            unsigned long long h2 = *(const unsigned long long*)&hds2[ng + nn][k];
            ffma2(accA[nn], h2, w01);
            ffma2(accB[nn], h2, w23);
        }
    }
    float4 b = __ldg((const float4*)&bd2[c * 4]);
#pragma unroll
    for (int nn = 0; nn < 8; nn++) {
        float2 vA = unpack2(accA[nn]);
        float2 vB = unpack2(accB[nn]);
        float4 o;
        o.x = fmaxf(vA.x + b.x, 0.f);
        o.y = fmaxf(vA.y + b.y, 0.f);
        o.z = fmaxf(vB.x + b.z, 0.f);
        o.w = fmaxf(vB.y + b.w, 0.f);
        *(float4*)&out[FEAT_OFF + (size_t)(nb + ng + nn) * D_FEATC + c * 4] = o;
    }
}

// ---------------- warp-MMA adjacency ----------------
// adj = sigmoid(z z^T) via mma.sync m16n8k16 bf16, hi/lo split as K=96 GEMM:
//   A'' = [Hi | Hi | Lo], B'' = [Hi | Lo | Hi]  ->  Hi Hi^T + Hi Lo^T + Lo Hi^T
// Per CTA: symmetric tile pair (it, jt), it <= jt, 128x128 each; 8 warps in 4x2 grid,
// each warp 32 rows x 64 cols. Padded smem (stride 104 bf16 = 208B): ldmatrix phases
// conflict-free (r*208 mod 128 distinct over 8 rows).
#define AW 104
#define ADJ_SMEM (2 * 128 * AW * 2)      // 53248 bytes

__global__ void __launch_bounds__(256) k_adj_wm(
    const float* __restrict__ zmat, float* __restrict__ out)
{
    extern __shared__ __nv_bfloat16 sm[];
    __nv_bfloat16* Asm = sm;                 // [128][AW]
    __nv_bfloat16* Bsm = sm + 128 * AW;      // [128][AW]

    const int t = threadIdx.x;
    const int wid = t >> 5;
    const int lane = t & 31;

    // triangular tile-pair decode
    const int T = 64;
    const int b = blockIdx.x;
    float disc = 129.0f * 129.0f - 8.0f * (float)b;
    int it = (int)((129.0f - sqrtf(disc)) * 0.5f);
    while (it > 0 && b < it * T - (it * (it - 1)) / 2) it--;
    while (b >= (it + 1) * T - ((it + 1) * it) / 2) it++;
    const int jt = it + (b - (it * T - (it * (it - 1)) / 2));

    // prologue: load z rows, bf16 hi/lo split, write padded smem (Hi duplicated)
    for (int idx = t; idx < 2048; idx += 256) {
        int half = idx >> 10;                 // 0 = A (tile it), 1 = B (tile jt)
        int rem  = idx & 1023;
        int row  = rem >> 3;
        int q    = rem & 7;                   // quad of 4 floats
        int tl   = half ? jt : it;
        float4 v = *(const float4*)&zmat[((size_t)tl * 128 + row) * 32 + q * 4];

        __nv_bfloat16 h0 = __float2bfloat16(v.x);
        __nv_bfloat16 h1 = __float2bfloat16(v.y);
        __nv_bfloat16 h2 = __float2bfloat16(v.z);
        __nv_bfloat16 h3 = __float2bfloat16(v.w);
        __nv_bfloat16 l0 = __float2bfloat16(v.x - __bfloat162float(h0));
        __nv_bfloat16 l1 = __float2bfloat16(v.y - __bfloat162float(h1));
        __nv_bfloat16 l2 = __float2bfloat16(v.z - __bfloat162float(h2));
        __nv_bfloat16 l3 = __float2bfloat16(v.w - __bfloat162float(h3));

        __nv_bfloat162 hp0 = __nv_bfloat162(h0, h1), hp1 = __nv_bfloat162(h2, h3);
        __nv_bfloat162 lp0 = __nv_bfloat162(l0, l1), lp1 = __nv_bfloat162(l2, l3);
        uint2 hw = make_uint2(*(uint32_t*)&hp0, *(uint32_t*)&hp1);
        uint2 lw = make_uint2(*(uint32_t*)&lp0, *(uint32_t*)&lp1);

        __nv_bfloat16* base = (half ? Bsm : Asm) + row * AW + q * 4;
        if (!half) {
            *(uint2*)(base + 0)  = hw;        // Hi @ [0,32)
            *(uint2*)(base + 32) = hw;        // Hi @ [32,64)
            *(uint2*)(base + 64) = lw;        // Lo @ [64,96)
        } else {
            *(uint2*)(base + 0)  = hw;        // Hi @ [0,32)
            *(uint2*)(base + 32) = lw;        // Lo @ [32,64)
            *(uint2*)(base + 64) = hw;        // Hi @ [64,96)
        }
    }
    __syncthreads();

    // warp tile: wm in 0..3 (row block of 32), wn in 0..1 (col block of 64)
    const int wm = wid & 3;
    const int wn = wid >> 2;
    const int rowW = wm * 32;
    const int colW = wn * 64;

    float c[2][8][4];
#pragma unroll
    for (int mi = 0; mi < 2; mi++)
#pragma unroll
        for (int ni = 0; ni < 8; ni++)
#pragma unroll
            for (int r = 0; r < 4; r++) c[mi][ni][r] = 0.f;

    // ldmatrix base addresses
    const uint32_t aBase = smem_u32(Asm);
    const uint32_t bBase = smem_u32(Bsm);
    // A: lane l -> row rowW + mi*16 + (l%16), col k0 + (l/16)*8
    const int la_r = lane & 15;
    const int la_c = (lane >> 4) * 8;
    // B: lane l -> row colW + nb*16 + (l%8) + ((l/16)*8), col k0 + ((l>>3)&1)*8
    const int lb_r = (lane & 7) + ((lane >> 4) * 8);
    const int lb_c = ((lane >> 3) & 1) * 8;

#pragma unroll
    for (int kc = 0; kc < 6; kc++) {
        const int k0 = kc * 16;
        uint32_t a[2][4];
#pragma unroll
        for (int mi = 0; mi < 2; mi++) {
            uint32_t addr = aBase + ((rowW + mi * 16 + la_r) * AW + k0 + la_c) * 2;
            ldsm_x4(a[mi][0], a[mi][1], a[mi][2], a[mi][3], addr);
        }
        uint32_t bfr[8][2];
#pragma unroll
        for (int nb2 = 0; nb2 < 4; nb2++) {
            uint32_t addr = bBase + ((colW + nb2 * 16 + lb_r) * AW + k0 + lb_c) * 2;
            uint32_t t0, t1, t2, t3;
            ldsm_x4(t0, t1, t2, t3, addr);
            bfr[nb2 * 2 + 0][0] = t0; bfr[nb2 * 2 + 0][1] = t1;
            bfr[nb2 * 2 + 1][0] = t2; bfr[nb2 * 2 + 1][1] = t3;
        }
#pragma unroll
        for (int mi = 0; mi < 2; mi++)
#pragma unroll
            for (int ni = 0; ni < 8; ni++)
                mma_16816(c[mi][ni], a[mi], bfr[ni]);
    }

    // epilogue: sigmoid + stores
    // C frag mapping: c[mi][ni][0..3]: (r0, cc), (r0, cc+1), (r0+8, cc), (r0+8, cc+1)
    //   r0 = rowW + mi*16 + lane/4 ; cc = colW + ni*8 + (lane%4)*2
    const int rThr = lane >> 2;
    const int cThr = (lane & 3) * 2;
    const size_t gi0 = (size_t)it * 128;
    const size_t gj0 = (size_t)jt * 128;

#pragma unroll
    for (int mi = 0; mi < 2; mi++) {
#pragma unroll
        for (int ni = 0; ni < 8; ni++) {
            float s0 = sigf(c[mi][ni][0]);
            float s1 = sigf(c[mi][ni][1]);
            float s2 = sigf(c[mi][ni][2]);
            float s3 = sigf(c[mi][ni][3]);
            int r0 = rowW + mi * 16 + rThr;
            int cc = colW + ni * 8 + cThr;
            // main tile: row-major
            *(float2*)&out[(gi0 + r0)     * (size_t)N_NODESC + gj0 + cc] = make_float2(s0, s1);
            *(float2*)&out[(gi0 + r0 + 8) * (size_t)N_NODESC + gj0 + cc] = make_float2(s2, s3);
            if (it != jt) {
                // mirror: transposed
                out[(gj0 + cc)     * (size_t)N_NODESC + gi0 + r0]     = s0;
                out[(gj0 + cc + 1) * (size_t)N_NODESC + gi0 + r0]     = s1;
                out[(gj0 + cc)     * (size_t)N_NODESC + gi0 + r0 + 8] = s2;
                out[(gj0 + cc + 1) * (size_t)N_NODESC + gi0 + r0 + 8] = s3;
            }
        }
    }
}

// ---------------- launch ----------------
extern "C" void kernel_launch(void* const* d_in, const int* in_sizes, int n_in,
                              void* d_out, int out_size)
{
    const float* X   = (const float*)d_in[0];
    const int*   esrc= (const int*)  d_in[1];
    const int*   edst= (const int*)  d_in[2];
    const float* ew  = (const float*)d_in[3];
    const float* Wg1 = (const float*)d_in[4];
    const float* bg1 = (const float*)d_in[5];
    const float* Wg2 = (const float*)d_in[6];
    const float* bg2 = (const float*)d_in[7];
    const float* We1 = (const float*)d_in[8];
    const float* be1 = (const float*)d_in[9];
    const float* We2 = (const float*)d_in[10];
    const float* be2 = (const float*)d_in[11];
    const float* Wd1 = (const float*)d_in[12];
    const float* bd1 = (const float*)d_in[13];
    const float* Wd2 = (const float*)d_in[14];
    const float* bd2 = (const float*)d_in[15];
    float* out = (float*)d_out;

    static int smemSet = 0;
    if (!smemSet) {
        cudaFuncSetAttribute(k_adj_wm, cudaFuncAttributeMaxDynamicSharedMemorySize, ADJ_SMEM);
        smemSet = 1;
    }

    k_transform1<<<128, 256>>>(X, Wg1, We1, be1);
    k_agg1      <<<8192, 256>>>(esrc, edst, ew);
    k_layer2pre <<<512, 256>>>(bg1, Wg2);
    k_agg2      <<<4096, 256>>>(esrc, edst, ew);
    k_node      <<<64, 128>>>(bg2, We2, be2, Wd1, bd1, out);
    k_feat      <<<512, 256>>>(Wd2, bd2, out);
    k_adj_wm    <<<2080, 256, ADJ_SMEM>>>(out + Z_OFF, out);
}